// round 1
// baseline (speedup 1.0000x reference)
#include <cuda_runtime.h>

#define N_NODES 20000
#define N_EDGES 160000
#define E_TOT   180000     // edges + self loops
#define FEAT    512
#define HEADS   4
#define HC      2048       // HEADS * FEAT
#define NEG_SLOPE 0.2f

// ---------------- scratch (static device globals; no allocations) ----------
__device__ float    g_xl[(size_t)N_NODES * HC];      // 163.8 MB
__device__ float    g_xr[(size_t)N_NODES * HC];      // 163.8 MB
__device__ float    g_agg[(size_t)N_NODES * FEAT];   // 41 MB
__device__ float    g_e[E_TOT * HEADS];
__device__ float    g_alpha[E_TOT * HEADS];
__device__ unsigned g_mu[N_NODES * HEADS];
__device__ float    g_denom[N_NODES * HEADS];

// ---------------- helpers --------------------------------------------------
__device__ __forceinline__ unsigned f2tf(float f) {
    unsigned u;
    asm("cvt.rna.tf32.f32 %0, %1;" : "=r"(u) : "f"(f));
    return u;
}

// order-preserving float -> unsigned encoding for atomicMax
__device__ __forceinline__ unsigned fenc(float f) {
    int b = __float_as_int(f);
    return (b >= 0) ? ((unsigned)b | 0x80000000u) : ~((unsigned)b);
}
__device__ __forceinline__ float fdec(unsigned u) {
    int b = (u & 0x80000000u) ? (int)(u & 0x7FFFFFFFu) : ~((int)u);
    return __int_as_float(b);
}

__device__ __forceinline__ void mma_tf32(float* c, const unsigned* a, const unsigned* b) {
    asm volatile(
        "mma.sync.aligned.m16n8k8.row.col.f32.tf32.tf32.f32 "
        "{%0,%1,%2,%3}, {%4,%5,%6,%7}, {%8,%9}, {%0,%1,%2,%3};\n"
        : "+f"(c[0]), "+f"(c[1]), "+f"(c[2]), "+f"(c[3])
        : "r"(a[0]), "r"(a[1]), "r"(a[2]), "r"(a[3]), "r"(b[0]), "r"(b[1]));
}

// ---------------- init -----------------------------------------------------
__global__ void init_kernel() {
    int i = blockIdx.x * blockDim.x + threadIdx.x;
    int stride = gridDim.x * blockDim.x;
    for (int k = i; k < N_NODES * FEAT; k += stride) g_agg[k] = 0.0f;
    for (int k = i; k < N_NODES * HEADS; k += stride) {
        g_mu[k] = 0u;          // encodes "below -inf"
        g_denom[k] = 0.0f;
    }
}

// ---------------- fused GEMM: xl = x@W_l (z=0), xr = x@W_r (z=1) -----------
// M=20000, K=512, N=2048. BM=128, BN=128, BK=32, 256 threads, 8 warps (2x4),
// warp tile 64x32 -> 4x4 m16n8k8 tiles.
__global__ __launch_bounds__(256, 2)
void gemm_tf32_kernel(const float* __restrict__ x,
                      const float* __restrict__ Wl,
                      const float* __restrict__ Wr) {
    const int z = blockIdx.z;
    const float* __restrict__ B = z ? Wr : Wl;
    float* __restrict__ C = z ? g_xr : g_xl;

    const int bm = blockIdx.y * 128;
    const int bn = blockIdx.x * 128;

    __shared__ unsigned As[128][36];   // m-major, padded: conflict-free frag loads
    __shared__ unsigned Bs[32][136];   // k-major, padded

    const int tid  = threadIdx.x;
    const int lane = tid & 31;
    const int warp = tid >> 5;
    const int wm = (warp & 1) * 64;    // warp row offset within block
    const int wn = (warp >> 1) * 32;   // warp col offset within block

    float acc[4][4][4];
#pragma unroll
    for (int i = 0; i < 4; i++)
#pragma unroll
        for (int j = 0; j < 4; j++)
#pragma unroll
            for (int r = 0; r < 4; r++) acc[i][j][r] = 0.0f;

    for (int k0 = 0; k0 < FEAT; k0 += 32) {
        // load A tile 128x32 (4 float4 per thread, predicated on M)
        {
            int row = tid >> 3;            // 0..31
            int kk  = (tid & 7) * 4;       // 0..28
#pragma unroll
            for (int r = 0; r < 4; r++) {
                int rl = row + r * 32;
                int rg = bm + rl;
                float4 v = make_float4(0.f, 0.f, 0.f, 0.f);
                if (rg < N_NODES)
                    v = *(const float4*)(x + (size_t)rg * FEAT + k0 + kk);
                uint4 u;
                u.x = f2tf(v.x); u.y = f2tf(v.y); u.z = f2tf(v.z); u.w = f2tf(v.w);
                *(uint4*)&As[rl][kk] = u;
            }
        }
        // load B tile 32x128 (4 float4 per thread)
        {
            int nn = (tid & 31) * 4;       // 0..124
            int kk = tid >> 5;             // 0..7
#pragma unroll
            for (int r = 0; r < 4; r++) {
                int kr = kk + r * 8;
                float4 v = *(const float4*)(B + (size_t)(k0 + kr) * HC + bn + nn);
                uint4 u;
                u.x = f2tf(v.x); u.y = f2tf(v.y); u.z = f2tf(v.z); u.w = f2tf(v.w);
                *(uint4*)&Bs[kr][nn] = u;
            }
        }
        __syncthreads();

#pragma unroll
        for (int ks = 0; ks < 4; ks++) {
            const int k8 = ks * 8;
            unsigned a[4][4], b[4][2];
#pragma unroll
            for (int mt = 0; mt < 4; mt++) {
                int r0 = wm + mt * 16 + (lane >> 2);
                int c0 = k8 + (lane & 3);
                a[mt][0] = As[r0][c0];
                a[mt][1] = As[r0 + 8][c0];
                a[mt][2] = As[r0][c0 + 4];
                a[mt][3] = As[r0 + 8][c0 + 4];
            }
#pragma unroll
            for (int nt = 0; nt < 4; nt++) {
                int nb = wn + nt * 8 + (lane >> 2);
                b[nt][0] = Bs[k8 + (lane & 3)][nb];
                b[nt][1] = Bs[k8 + 4 + (lane & 3)][nb];
            }
#pragma unroll
            for (int mt = 0; mt < 4; mt++)
#pragma unroll
                for (int nt = 0; nt < 4; nt++)
                    mma_tf32(acc[mt][nt], a[mt], b[nt]);
        }
        __syncthreads();
    }

    // epilogue
#pragma unroll
    for (int mt = 0; mt < 4; mt++) {
        int r0 = bm + wm + mt * 16 + (lane >> 2);
#pragma unroll
        for (int nt = 0; nt < 4; nt++) {
            int col = bn + wn + nt * 8 + (lane & 3) * 2;
            if (r0 < N_NODES) {
                float2 v = make_float2(acc[mt][nt][0], acc[mt][nt][1]);
                *(float2*)(C + (size_t)r0 * HC + col) = v;
            }
            if (r0 + 8 < N_NODES) {
                float2 v = make_float2(acc[mt][nt][2], acc[mt][nt][3]);
                *(float2*)(C + (size_t)(r0 + 8) * HC + col) = v;
            }
        }
    }
}

// ---------------- edge scores + segment max --------------------------------
// one warp per edge
__global__ void score_kernel(const int* __restrict__ ei,
                             const float* __restrict__ att) {
    int w = (blockIdx.x * blockDim.x + threadIdx.x) >> 5;
    int lane = threadIdx.x & 31;
    if (w >= E_TOT) return;
    int src, dst;
    if (w < N_EDGES) { src = ei[w]; dst = ei[N_EDGES + w]; }
    else             { src = dst = w - N_EDGES; }

    const float4* __restrict__ xl = (const float4*)(g_xl + (size_t)src * HC);
    const float4* __restrict__ xr = (const float4*)(g_xr + (size_t)dst * HC);
    const float4* __restrict__ at = (const float4*)att;   // [H*C] contiguous

    float accs[4] = {0.f, 0.f, 0.f, 0.f};
#pragma unroll
    for (int it = 0; it < 16; it++) {
        int o = it * 32 + lane;          // float4 index in [0,512)
        float4 a = xl[o];
        float4 b = xr[o];
        float4 t = at[o];
        float ux = a.x + b.x, uy = a.y + b.y, uz = a.z + b.z, uw = a.w + b.w;
        ux = ux > 0.f ? ux : NEG_SLOPE * ux;
        uy = uy > 0.f ? uy : NEG_SLOPE * uy;
        uz = uz > 0.f ? uz : NEG_SLOPE * uz;
        uw = uw > 0.f ? uw : NEG_SLOPE * uw;
        accs[it >> 2] += ux * t.x + uy * t.y + uz * t.z + uw * t.w;
    }
#pragma unroll
    for (int h = 0; h < 4; h++)
#pragma unroll
        for (int off = 16; off; off >>= 1)
            accs[h] += __shfl_xor_sync(0xFFFFFFFFu, accs[h], off);

    if (lane == 0) {
#pragma unroll
        for (int h = 0; h < 4; h++) {
            g_e[w * 4 + h] = accs[h];
            atomicMax(&g_mu[dst * 4 + h], fenc(accs[h]));
        }
    }
}

// ---------------- alpha = exp(e - m), denom = segment_sum ------------------
__global__ void alpha_kernel(const int* __restrict__ ei) {
    int t = blockIdx.x * blockDim.x + threadIdx.x;
    if (t >= E_TOT * HEADS) return;
    int k = t >> 2, h = t & 3;
    int dst = (k < N_EDGES) ? ei[N_EDGES + k] : (k - N_EDGES);
    float m = fdec(g_mu[dst * 4 + h]);
    float a = expf(g_e[t] - m);
    g_alpha[t] = a;
    atomicAdd(&g_denom[dst * 4 + h], a);
}

// ---------------- aggregation: agg[dst] += sum_h (alpha/denom/H)*xl[src] ---
// one warp per edge; head-sum folded so only 512 atomics per edge
__global__ void agg_kernel(const int* __restrict__ ei) {
    int w = (blockIdx.x * blockDim.x + threadIdx.x) >> 5;
    int lane = threadIdx.x & 31;
    if (w >= E_TOT) return;
    int src, dst;
    if (w < N_EDGES) { src = ei[w]; dst = ei[N_EDGES + w]; }
    else             { src = dst = w - N_EDGES; }

    float wt[4];
#pragma unroll
    for (int h = 0; h < 4; h++)
        wt[h] = 0.25f * g_alpha[w * 4 + h] / g_denom[dst * 4 + h];

    const float4* __restrict__ xl = (const float4*)(g_xl + (size_t)src * HC);
    float* __restrict__ out = g_agg + (size_t)dst * FEAT;

#pragma unroll
    for (int it = 0; it < 4; it++) {
        int c4 = it * 32 + lane;            // float4 idx in [0,128)
        float4 v0 = xl[c4];
        float4 v1 = xl[128 + c4];
        float4 v2 = xl[256 + c4];
        float4 v3 = xl[384 + c4];
        float rx = wt[0] * v0.x + wt[1] * v1.x + wt[2] * v2.x + wt[3] * v3.x;
        float ry = wt[0] * v0.y + wt[1] * v1.y + wt[2] * v2.y + wt[3] * v3.y;
        float rz = wt[0] * v0.z + wt[1] * v1.z + wt[2] * v2.z + wt[3] * v3.z;
        float rw = wt[0] * v0.w + wt[1] * v1.w + wt[2] * v2.w + wt[3] * v3.w;
        int c = c4 * 4;
        atomicAdd(out + c + 0, rx);
        atomicAdd(out + c + 1, ry);
        atomicAdd(out + c + 2, rz);
        atomicAdd(out + c + 3, rw);
    }
}

// ---------------- head mean + bias + classifier ----------------------------
// one warp per node
__global__ void head_kernel(const float* __restrict__ bias,
                            const float* __restrict__ Wc,
                            const float* __restrict__ bc,
                            float* __restrict__ out) {
    int n = (blockIdx.x * blockDim.x + threadIdx.x) >> 5;
    int lane = threadIdx.x & 31;
    if (n >= N_NODES) return;

    const float4* __restrict__ ag = (const float4*)(g_agg + (size_t)n * FEAT);
    const float4* __restrict__ bi = (const float4*)bias;

    float a0 = 0.f, a1 = 0.f;
#pragma unroll
    for (int it = 0; it < 4; it++) {
        int c4 = it * 32 + lane;            // float4 idx in [0,128)
        float4 v = ag[c4];
        float4 b = bi[c4];
        float o0 = v.x + b.x, o1 = v.y + b.y, o2 = v.z + b.z, o3 = v.w + b.w;
        const float4* w4 = (const float4*)(Wc + (size_t)c4 * 8);
        float4 wA = w4[0];   // rows c, c+1 (cols 0,1 each)
        float4 wB = w4[1];   // rows c+2, c+3
        a0 += o0 * wA.x + o1 * wA.z + o2 * wB.x + o3 * wB.z;
        a1 += o0 * wA.y + o1 * wA.w + o2 * wB.y + o3 * wB.w;
    }
#pragma unroll
    for (int off = 16; off; off >>= 1) {
        a0 += __shfl_xor_sync(0xFFFFFFFFu, a0, off);
        a1 += __shfl_xor_sync(0xFFFFFFFFu, a1, off);
    }
    if (lane == 0) {
        out[n * 2 + 0] = a0 + bc[0];
        out[n * 2 + 1] = a1 + bc[1];
    }
}

// ---------------- launch ---------------------------------------------------
extern "C" void kernel_launch(void* const* d_in, const int* in_sizes, int n_in,
                              void* d_out, int out_size) {
    const float* x    = (const float*)d_in[0];
    const int*   ei   = (const int*)  d_in[1];
    const float* Wl   = (const float*)d_in[2];
    const float* Wr   = (const float*)d_in[3];
    const float* att  = (const float*)d_in[4];
    const float* bias = (const float*)d_in[5];
    const float* Wc   = (const float*)d_in[6];
    const float* bc   = (const float*)d_in[7];
    float* out = (float*)d_out;

    init_kernel<<<2560, 256>>>();

    dim3 ggrid(HC / 128, (N_NODES + 127) / 128, 2);   // (16, 157, 2)
    gemm_tf32_kernel<<<ggrid, 256>>>(x, Wl, Wr);

    score_kernel<<<(E_TOT + 7) / 8, 256>>>(ei, att);            // warp/edge
    alpha_kernel<<<(E_TOT * HEADS + 255) / 256, 256>>>(ei);
    agg_kernel<<<(E_TOT + 7) / 8, 256>>>(ei);                   // warp/edge
    head_kernel<<<(N_NODES + 7) / 8, 256>>>(bias, Wc, bc, out); // warp/node
}

// round 3
// speedup vs baseline: 1.4835x; 1.4835x over previous
#include <cuda_runtime.h>
#include <cuda_fp16.h>
#include <cstdint>

#define N_NODES 20000
#define N_EDGES 160000
#define E_TOT   180000     // edges + self loops
#define FEAT    512
#define HEADS   4
#define HC      2048       // HEADS * FEAT
#define NEG_SLOPE 0.2f

// ---------------- scratch (static device globals; no allocations) ----------
__device__ __half   g_xh[(size_t)N_NODES * FEAT];    // x in half, 20.5 MB
__device__ __half   g_WT[2][(size_t)HC * FEAT];      // W^T in half, 2x2 MB
__device__ __half   g_xl[(size_t)N_NODES * HC];      // 82 MB
__device__ __half   g_xr[(size_t)N_NODES * HC];      // 82 MB
__device__ float    g_agg[(size_t)N_NODES * FEAT];   // 41 MB
__device__ float    g_e[E_TOT * HEADS];
__device__ float    g_alpha[E_TOT * HEADS];
__device__ unsigned g_mu[N_NODES * HEADS];
__device__ float    g_denom[N_NODES * HEADS];

// ---------------- helpers --------------------------------------------------
__device__ __forceinline__ unsigned fenc(float f) {
    int b = __float_as_int(f);
    return (b >= 0) ? ((unsigned)b | 0x80000000u) : ~((unsigned)b);
}
__device__ __forceinline__ float fdec(unsigned u) {
    int b = (u & 0x80000000u) ? (int)(u & 0x7FFFFFFFu) : ~((int)u);
    return __int_as_float(b);
}
__device__ __forceinline__ uint32_t smem_u32(const void* p) {
    uint32_t a;
    asm("{ .reg .u64 t; cvta.to.shared.u64 t, %1; cvt.u32.u64 %0, t; }" : "=r"(a) : "l"(p));
    return a;
}
__device__ __forceinline__ void cp_async16(uint32_t dst, const void* src, int bytes) {
    asm volatile("cp.async.ca.shared.global [%0], [%1], 16, %2;"
                 :: "r"(dst), "l"(src), "r"(bytes) : "memory");
}
#define CP_COMMIT() asm volatile("cp.async.commit_group;" ::: "memory")
#define CP_WAIT1()  asm volatile("cp.async.wait_group 1;" ::: "memory")
#define CP_WAIT0()  asm volatile("cp.async.wait_group 0;" ::: "memory")

__device__ __forceinline__ void mma_f16(float* c, const unsigned* a, const unsigned* b) {
    asm volatile(
        "mma.sync.aligned.m16n8k16.row.col.f32.f16.f16.f32 "
        "{%0,%1,%2,%3}, {%4,%5,%6,%7}, {%8,%9}, {%0,%1,%2,%3};\n"
        : "+f"(c[0]), "+f"(c[1]), "+f"(c[2]), "+f"(c[3])
        : "r"(a[0]), "r"(a[1]), "r"(a[2]), "r"(a[3]), "r"(b[0]), "r"(b[1]));
}

// ---------------- init -----------------------------------------------------
__global__ void init_kernel() {
    int i = blockIdx.x * blockDim.x + threadIdx.x;
    int stride = gridDim.x * blockDim.x;
    for (int k = i; k < N_NODES * FEAT; k += stride) g_agg[k] = 0.0f;
    for (int k = i; k < N_NODES * HEADS; k += stride) {
        g_mu[k] = 0u;
        g_denom[k] = 0.0f;
    }
}

// ---------------- x -> half ------------------------------------------------
__global__ void xcvt_kernel(const float* __restrict__ x) {
    int i = blockIdx.x * blockDim.x + threadIdx.x;   // one per 8 floats
    if (i >= N_NODES * FEAT / 8) return;
    float4 a = ((const float4*)x)[2 * i];
    float4 b = ((const float4*)x)[2 * i + 1];
    union { __half2 h[4]; uint4 u; } pk;
    pk.h[0] = __floats2half2_rn(a.x, a.y);
    pk.h[1] = __floats2half2_rn(a.z, a.w);
    pk.h[2] = __floats2half2_rn(b.x, b.y);
    pk.h[3] = __floats2half2_rn(b.z, b.w);
    ((uint4*)g_xh)[i] = pk.u;
}

// ---------------- W [512,2048] -> W^T [2048,512] half ----------------------
__global__ void wtrans_kernel(const float* __restrict__ Wl,
                              const float* __restrict__ Wr) {
    __shared__ float t[32][33];
    const float* W = blockIdx.z ? Wr : Wl;
    __half* WT = g_WT[blockIdx.z];
    int n0 = blockIdx.x * 32, k0 = blockIdx.y * 32;
    int tx = threadIdx.x, ty = threadIdx.y;   // (32,8)
#pragma unroll
    for (int j = 0; j < 4; j++)
        t[ty + j * 8][tx] = W[(size_t)(k0 + ty + j * 8) * HC + n0 + tx];
    __syncthreads();
#pragma unroll
    for (int j = 0; j < 4; j++)
        WT[(size_t)(n0 + ty + j * 8) * FEAT + k0 + tx] = __float2half_rn(t[tx][ty + j * 8]);
}

// ---------------- fp16 mma.sync GEMM with cp.async pipeline ----------------
// C[20000,2048](half) = xh[20000,512] @ W; B = WT (K-major rows).
// BM=BN=128, BK=32. 256 thr, 8 warps (2x4), warp tile 64x32.
// SMEM rows: 32 halfs = 64B data + 16B pad = 80B stride (conflict-free b32 frags).
#define ROWB 80

__global__ __launch_bounds__(256, 2)
void gemm_f16_kernel() {
    __shared__ __align__(16) char smA[2][128 * ROWB];
    __shared__ __align__(16) char smB[2][128 * ROWB];

    const int z  = blockIdx.z;
    const __half* __restrict__ BT = g_WT[z];
    __half* __restrict__ C = z ? g_xr : g_xl;

    const int bm = blockIdx.y * 128;
    const int bn = blockIdx.x * 128;

    const int tid  = threadIdx.x;
    const int lane = tid & 31;
    const int warp = tid >> 5;
    const int wm = (warp & 1) * 64;
    const int wn = (warp >> 1) * 32;

    const int lr = tid >> 1;                 // 0..127 row for cp.async
    const int lc = (tid & 1) * 2;            // 16B-chunk base (0 or 2)

    const uint32_t sA[2] = { smem_u32(smA[0]), smem_u32(smA[1]) };
    const uint32_t sB[2] = { smem_u32(smB[0]), smem_u32(smB[1]) };
    const __half* aRow = g_xh + (size_t)(bm + lr) * FEAT;
    const int aOK = (bm + lr < N_NODES) ? 16 : 0;
    const __half* bRow = BT + (size_t)(bn + lr) * FEAT;

    float acc[4][4][4];
#pragma unroll
    for (int i = 0; i < 4; i++)
#pragma unroll
        for (int j = 0; j < 4; j++)
#pragma unroll
            for (int r = 0; r < 4; r++) acc[i][j][r] = 0.0f;

#define PREFETCH(chunk, buf) do {                                           \
    int _k0 = (chunk) * 32;                                                 \
    _Pragma("unroll")                                                       \
    for (int j = 0; j < 2; j++) {                                           \
        int c16 = lc + j;                                                   \
        cp_async16(sA[buf] + lr * ROWB + c16 * 16, aRow + _k0 + c16 * 8, aOK); \
        cp_async16(sB[buf] + lr * ROWB + c16 * 16, bRow + _k0 + c16 * 8, 16); \
    }                                                                       \
} while (0)

    PREFETCH(0, 0);
    CP_COMMIT();

    for (int chunk = 0; chunk < 16; chunk++) {
        const int buf = chunk & 1;
        if (chunk < 15) {
            PREFETCH(chunk + 1, buf ^ 1);
            CP_COMMIT();
            CP_WAIT1();
        } else {
            CP_WAIT0();
        }
        __syncthreads();

        const char* aB = smA[buf];
        const char* bB = smB[buf];
#pragma unroll
        for (int ks = 0; ks < 2; ks++) {
            const int wbase = (ks * 8 + (lane & 3)) * 4;   // byte offset in row
            unsigned a[4][4], b[4][2];
#pragma unroll
            for (int mt = 0; mt < 4; mt++) {
                int r0 = wm + mt * 16 + (lane >> 2);
                a[mt][0] = *(const unsigned*)(aB + r0 * ROWB + wbase);
                a[mt][1] = *(const unsigned*)(aB + (r0 + 8) * ROWB + wbase);
                a[mt][2] = *(const unsigned*)(aB + r0 * ROWB + wbase + 16);
                a[mt][3] = *(const unsigned*)(aB + (r0 + 8) * ROWB + wbase + 16);
            }
#pragma unroll
            for (int nt = 0; nt < 4; nt++) {
                int nb = wn + nt * 8 + (lane >> 2);
                b[nt][0] = *(const unsigned*)(bB + nb * ROWB + wbase);
                b[nt][1] = *(const unsigned*)(bB + nb * ROWB + wbase + 16);
            }
#pragma unroll
            for (int mt = 0; mt < 4; mt++)
#pragma unroll
                for (int nt = 0; nt < 4; nt++)
                    mma_f16(acc[mt][nt], a[mt], b[nt]);
        }
        __syncthreads();
    }

    // epilogue: store half
#pragma unroll
    for (int mt = 0; mt < 4; mt++) {
        int r0 = bm + wm + mt * 16 + (lane >> 2);
#pragma unroll
        for (int nt = 0; nt < 4; nt++) {
            int col = bn + wn + nt * 8 + (lane & 3) * 2;
            if (r0 < N_NODES)
                *(__half2*)(C + (size_t)r0 * HC + col) =
                    __floats2half2_rn(acc[mt][nt][0], acc[mt][nt][1]);
            if (r0 + 8 < N_NODES)
                *(__half2*)(C + (size_t)(r0 + 8) * HC + col) =
                    __floats2half2_rn(acc[mt][nt][2], acc[mt][nt][3]);
        }
    }
}

// ---------------- edge scores + segment max (warp/edge, half gathers) ------
__global__ void score_kernel(const int* __restrict__ ei,
                             const float* __restrict__ att) {
    int w = (blockIdx.x * blockDim.x + threadIdx.x) >> 5;
    int lane = threadIdx.x & 31;
    if (w >= E_TOT) return;
    int src, dst;
    if (w < N_EDGES) { src = ei[w]; dst = ei[N_EDGES + w]; }
    else             { src = dst = w - N_EDGES; }

    const uint4* __restrict__ xl = (const uint4*)(g_xl + (size_t)src * HC);
    const uint4* __restrict__ xr = (const uint4*)(g_xr + (size_t)dst * HC);
    const float4* __restrict__ at4 = (const float4*)att;

    float accs[4] = {0.f, 0.f, 0.f, 0.f};
#pragma unroll
    for (int it = 0; it < 8; it++) {
        int g = it * 32 + lane;             // uint4 group (8 halfs); head = it>>1
        uint4 a = xl[g];
        uint4 b = xr[g];
        float4 t0 = at4[2 * g], t1 = at4[2 * g + 1];
        const __half2* ha = (const __half2*)&a;
        const __half2* hb = (const __half2*)&b;
        float tt[8] = {t0.x, t0.y, t0.z, t0.w, t1.x, t1.y, t1.z, t1.w};
        float s = 0.f;
#pragma unroll
        for (int j = 0; j < 4; j++) {
            float2 fa = __half22float2(ha[j]);
            float2 fb = __half22float2(hb[j]);
            float u0 = fa.x + fb.x, u1 = fa.y + fb.y;
            u0 = u0 > 0.f ? u0 : NEG_SLOPE * u0;
            u1 = u1 > 0.f ? u1 : NEG_SLOPE * u1;
            s += u0 * tt[2 * j] + u1 * tt[2 * j + 1];
        }
        accs[it >> 1] += s;
    }
#pragma unroll
    for (int h = 0; h < 4; h++)
#pragma unroll
        for (int off = 16; off; off >>= 1)
            accs[h] += __shfl_xor_sync(0xFFFFFFFFu, accs[h], off);

    if (lane == 0) {
#pragma unroll
        for (int h = 0; h < 4; h++) {
            g_e[w * 4 + h] = accs[h];
            atomicMax(&g_mu[dst * 4 + h], fenc(accs[h]));
        }
    }
}

// ---------------- alpha = exp(e - m), denom = segment_sum ------------------
__global__ void alpha_kernel(const int* __restrict__ ei) {
    int t = blockIdx.x * blockDim.x + threadIdx.x;
    if (t >= E_TOT * HEADS) return;
    int k = t >> 2, h = t & 3;
    int dst = (k < N_EDGES) ? ei[N_EDGES + k] : (k - N_EDGES);
    float m = fdec(g_mu[dst * 4 + h]);
    float a = expf(g_e[t] - m);
    g_alpha[t] = a;
    atomicAdd(&g_denom[dst * 4 + h], a);
}

// ---------------- aggregation (warp/edge, half gathers, fp32 atomics) ------
__global__ void agg_kernel(const int* __restrict__ ei) {
    int w = (blockIdx.x * blockDim.x + threadIdx.x) >> 5;
    int lane = threadIdx.x & 31;
    if (w >= E_TOT) return;
    int src, dst;
    if (w < N_EDGES) { src = ei[w]; dst = ei[N_EDGES + w]; }
    else             { src = dst = w - N_EDGES; }

    float wt[4];
#pragma unroll
    for (int h = 0; h < 4; h++)
        wt[h] = 0.25f * g_alpha[w * 4 + h] / g_denom[dst * 4 + h];

    const uint2* __restrict__ row = (const uint2*)(g_xl + (size_t)src * HC);
    float* __restrict__ out = g_agg + (size_t)dst * FEAT;

#pragma unroll
    for (int it = 0; it < 4; it++) {
        int g = it * 32 + lane;             // 4-half group within head, < 128
        float rx = 0.f, ry = 0.f, rz = 0.f, rw = 0.f;
#pragma unroll
        for (int h = 0; h < 4; h++) {
            uint2 u = row[h * 128 + g];
            float2 f0 = __half22float2(*(const __half2*)&u.x);
            float2 f1 = __half22float2(*(const __half2*)&u.y);
            rx += wt[h] * f0.x; ry += wt[h] * f0.y;
            rz += wt[h] * f1.x; rw += wt[h] * f1.y;
        }
        int c = g * 4;
        atomicAdd(out + c + 0, rx);
        atomicAdd(out + c + 1, ry);
        atomicAdd(out + c + 2, rz);
        atomicAdd(out + c + 3, rw);
    }
}

// ---------------- head mean + bias + classifier (warp/node) ----------------
__global__ void head_kernel(const float* __restrict__ bias,
                            const float* __restrict__ Wc,
                            const float* __restrict__ bc,
                            float* __restrict__ out) {
    int n = (blockIdx.x * blockDim.x + threadIdx.x) >> 5;
    int lane = threadIdx.x & 31;
    if (n >= N_NODES) return;

    const float4* __restrict__ ag = (const float4*)(g_agg + (size_t)n * FEAT);
    const float4* __restrict__ bi = (const float4*)bias;

    float a0 = 0.f, a1 = 0.f;
#pragma unroll
    for (int it = 0; it < 4; it++) {
        int c4 = it * 32 + lane;
        float4 v = ag[c4];
        float4 b = bi[c4];
        float o0 = v.x + b.x, o1 = v.y + b.y, o2 = v.z + b.z, o3 = v.w + b.w;
        const float4* w4 = (const float4*)(Wc + (size_t)c4 * 8);
        float4 wA = w4[0];
        float4 wB = w4[1];
        a0 += o0 * wA.x + o1 * wA.z + o2 * wB.x + o3 * wB.z;
        a1 += o0 * wA.y + o1 * wA.w + o2 * wB.y + o3 * wB.w;
    }
#pragma unroll
    for (int off = 16; off; off >>= 1) {
        a0 += __shfl_xor_sync(0xFFFFFFFFu, a0, off);
        a1 += __shfl_xor_sync(0xFFFFFFFFu, a1, off);
    }
    if (lane == 0) {
        out[n * 2 + 0] = a0 + bc[0];
        out[n * 2 + 1] = a1 + bc[1];
    }
}

// ---------------- launch ---------------------------------------------------
extern "C" void kernel_launch(void* const* d_in, const int* in_sizes, int n_in,
                              void* d_out, int out_size) {
    const float* x    = (const float*)d_in[0];
    const int*   ei   = (const int*)  d_in[1];
    const float* Wl   = (const float*)d_in[2];
    const float* Wr   = (const float*)d_in[3];
    const float* att  = (const float*)d_in[4];
    const float* bias = (const float*)d_in[5];
    const float* Wc   = (const float*)d_in[6];
    const float* bc   = (const float*)d_in[7];
    float* out = (float*)d_out;

    init_kernel<<<2560, 256>>>();
    xcvt_kernel<<<(N_NODES * FEAT / 8 + 255) / 256, 256>>>(x);
    wtrans_kernel<<<dim3(HC / 32, FEAT / 32, 2), dim3(32, 8)>>>(Wl, Wr);

    dim3 ggrid(HC / 128, (N_NODES + 127) / 128, 2);   // (16, 157, 2)
    gemm_f16_kernel<<<ggrid, 256>>>();

    score_kernel<<<(E_TOT + 7) / 8, 256>>>(ei, att);
    alpha_kernel<<<(E_TOT * HEADS + 255) / 256, 256>>>(ei);
    agg_kernel<<<(E_TOT + 7) / 8, 256>>>(ei);
    head_kernel<<<(N_NODES + 7) / 8, 256>>>(bias, Wc, bc, out);
}

// round 4
// speedup vs baseline: 1.6239x; 1.0946x over previous
#include <cuda_runtime.h>
#include <cuda_fp16.h>
#include <cstdint>

#define N_NODES 20000
#define N_EDGES 160000
#define E_TOT   180000     // edges + self loops
#define FEAT    512
#define HEADS   4
#define HC      2048       // HEADS * FEAT
#define NEG_SLOPE 0.2f

// ---------------- scratch (static device globals; no allocations) ----------
__device__ __half   g_xh[(size_t)N_NODES * FEAT];    // x in half, 20.5 MB
__device__ __half   g_WT[2][(size_t)HC * FEAT];      // W^T in half, 2x2 MB
__device__ __half   g_xl[(size_t)N_NODES * HC];      // 82 MB
__device__ __half   g_xr[(size_t)N_NODES * HC];      // 82 MB
__device__ float    g_agg[(size_t)N_NODES * FEAT];   // 41 MB
__device__ float    g_e[E_TOT * HEADS];
__device__ float    g_alpha[E_TOT * HEADS];
__device__ unsigned g_mu[N_NODES * HEADS];
__device__ float    g_denom[N_NODES * HEADS];

// ---------------- helpers --------------------------------------------------
__device__ __forceinline__ unsigned fenc(float f) {
    int b = __float_as_int(f);
    return (b >= 0) ? ((unsigned)b | 0x80000000u) : ~((unsigned)b);
}
__device__ __forceinline__ float fdec(unsigned u) {
    int b = (u & 0x80000000u) ? (int)(u & 0x7FFFFFFFu) : ~((int)u);
    return __int_as_float(b);
}
__device__ __forceinline__ uint32_t smem_u32(const void* p) {
    uint32_t a;
    asm("{ .reg .u64 t; cvta.to.shared.u64 t, %1; cvt.u32.u64 %0, t; }" : "=r"(a) : "l"(p));
    return a;
}
__device__ __forceinline__ void cp_async16(uint32_t dst, const void* src, int bytes) {
    asm volatile("cp.async.ca.shared.global [%0], [%1], 16, %2;"
                 :: "r"(dst), "l"(src), "r"(bytes) : "memory");
}
#define CP_COMMIT() asm volatile("cp.async.commit_group;" ::: "memory")
#define CP_WAIT1()  asm volatile("cp.async.wait_group 1;" ::: "memory")
#define CP_WAIT0()  asm volatile("cp.async.wait_group 0;" ::: "memory")

__device__ __forceinline__ void mma_f16(float* c, const unsigned* a, const unsigned* b) {
    asm volatile(
        "mma.sync.aligned.m16n8k16.row.col.f32.f16.f16.f32 "
        "{%0,%1,%2,%3}, {%4,%5,%6,%7}, {%8,%9}, {%0,%1,%2,%3};\n"
        : "+f"(c[0]), "+f"(c[1]), "+f"(c[2]), "+f"(c[3])
        : "r"(a[0]), "r"(a[1]), "r"(a[2]), "r"(a[3]), "r"(b[0]), "r"(b[1]));
}
__device__ __forceinline__ void ldsm_x4(unsigned& r0, unsigned& r1,
                                        unsigned& r2, unsigned& r3, uint32_t a) {
    asm volatile("ldmatrix.sync.aligned.m8n8.x4.shared.b16 {%0,%1,%2,%3}, [%4];"
                 : "=r"(r0), "=r"(r1), "=r"(r2), "=r"(r3) : "r"(a));
}

// ---------------- init -----------------------------------------------------
__global__ void init_kernel() {
    int i = blockIdx.x * blockDim.x + threadIdx.x;
    int stride = gridDim.x * blockDim.x;
    for (int k = i; k < N_NODES * FEAT; k += stride) g_agg[k] = 0.0f;
    for (int k = i; k < N_NODES * HEADS; k += stride) {
        g_mu[k] = 0u;
        g_denom[k] = 0.0f;
    }
}

// ---------------- x -> half ------------------------------------------------
__global__ void xcvt_kernel(const float* __restrict__ x) {
    int i = blockIdx.x * blockDim.x + threadIdx.x;   // one per 8 floats
    if (i >= N_NODES * FEAT / 8) return;
    float4 a = ((const float4*)x)[2 * i];
    float4 b = ((const float4*)x)[2 * i + 1];
    union { __half2 h[4]; uint4 u; } pk;
    pk.h[0] = __floats2half2_rn(a.x, a.y);
    pk.h[1] = __floats2half2_rn(a.z, a.w);
    pk.h[2] = __floats2half2_rn(b.x, b.y);
    pk.h[3] = __floats2half2_rn(b.z, b.w);
    ((uint4*)g_xh)[i] = pk.u;
}

// ---------------- W [512,2048] -> W^T [2048,512] half ----------------------
__global__ void wtrans_kernel(const float* __restrict__ Wl,
                              const float* __restrict__ Wr) {
    __shared__ float t[32][33];
    const float* W = blockIdx.z ? Wr : Wl;
    __half* WT = g_WT[blockIdx.z];
    int n0 = blockIdx.x * 32, k0 = blockIdx.y * 32;
    int tx = threadIdx.x, ty = threadIdx.y;   // (32,8)
#pragma unroll
    for (int j = 0; j < 4; j++)
        t[ty + j * 8][tx] = W[(size_t)(k0 + ty + j * 8) * HC + n0 + tx];
    __syncthreads();
#pragma unroll
    for (int j = 0; j < 4; j++)
        WT[(size_t)(n0 + ty + j * 8) * FEAT + k0 + tx] = __float2half_rn(t[tx][ty + j * 8]);
}

// ---------------- fp16 mma.sync GEMM, cp.async pipeline, ldmatrix frags ----
// C[20000,2048](half) = xh[20000,512] @ W; B = WT (K-major rows).
// BM=BN=128, BK=32. 256 thr, 8 warps (2x4), warp tile 64x32.
// SMEM rows: 32 halfs = 64B data + 16B pad = 80B stride (ldmatrix conflict-free).
#define ROWB 80

__global__ __launch_bounds__(256, 2)
void gemm_f16_kernel() {
    __shared__ __align__(16) char smA[2][128 * ROWB];
    __shared__ __align__(16) char smB[2][128 * ROWB];

    const int z  = blockIdx.z;
    const __half* __restrict__ BT = g_WT[z];
    __half* __restrict__ C = z ? g_xr : g_xl;

    const int bm = blockIdx.y * 128;
    const int bn = blockIdx.x * 128;

    const int tid  = threadIdx.x;
    const int lane = tid & 31;
    const int warp = tid >> 5;
    const int wm = (warp & 1) * 64;
    const int wn = (warp >> 1) * 32;

    const int lr = tid >> 1;                 // 0..127 row for cp.async
    const int lc = (tid & 1) * 2;            // 16B-chunk base (0 or 2)

    const uint32_t sA[2] = { smem_u32(smA[0]), smem_u32(smA[1]) };
    const uint32_t sB[2] = { smem_u32(smB[0]), smem_u32(smB[1]) };
    const __half* aRow = g_xh + (size_t)(bm + lr) * FEAT;
    const int aOK = (bm + lr < N_NODES) ? 16 : 0;
    const __half* bRow = BT + (size_t)(bn + lr) * FEAT;

    // ldmatrix lane addressing: row = lane&15, 16B col = lane>>4
    const int lrow = lane & 15;
    const int lcol = (lane >> 4) * 16;

    float acc[4][4][4];
#pragma unroll
    for (int i = 0; i < 4; i++)
#pragma unroll
        for (int j = 0; j < 4; j++)
#pragma unroll
            for (int r = 0; r < 4; r++) acc[i][j][r] = 0.0f;

#define PREFETCH(chunk, buf) do {                                           \
    int _k0 = (chunk) * 32;                                                 \
    _Pragma("unroll")                                                       \
    for (int j = 0; j < 2; j++) {                                           \
        int c16 = lc + j;                                                   \
        cp_async16(sA[buf] + lr * ROWB + c16 * 16, aRow + _k0 + c16 * 8, aOK); \
        cp_async16(sB[buf] + lr * ROWB + c16 * 16, bRow + _k0 + c16 * 8, 16); \
    }                                                                       \
} while (0)

    PREFETCH(0, 0);
    CP_COMMIT();

    for (int chunk = 0; chunk < 16; chunk++) {
        const int buf = chunk & 1;
        if (chunk < 15) {
            PREFETCH(chunk + 1, buf ^ 1);
            CP_COMMIT();
            CP_WAIT1();
        } else {
            CP_WAIT0();
        }
        __syncthreads();

        const uint32_t aBase = sA[buf] + lrow * ROWB + lcol;
        const uint32_t bBase = sB[buf] + lrow * ROWB + lcol;
#pragma unroll
        for (int ks = 0; ks < 2; ks++) {
            const int kb = ks * 32;          // byte offset of k16 slab
            unsigned a[4][4], bq[2][4];
#pragma unroll
            for (int mt = 0; mt < 4; mt++)
                ldsm_x4(a[mt][0], a[mt][1], a[mt][2], a[mt][3],
                        aBase + (wm + mt * 16) * ROWB + kb);
#pragma unroll
            for (int np = 0; np < 2; np++)
                ldsm_x4(bq[np][0], bq[np][1], bq[np][2], bq[np][3],
                        bBase + (wn + np * 16) * ROWB + kb);
#pragma unroll
            for (int mt = 0; mt < 4; mt++)
#pragma unroll
                for (int nt = 0; nt < 4; nt++) {
                    unsigned bfr[2] = { bq[nt >> 1][(nt & 1)],
                                        bq[nt >> 1][(nt & 1) + 2] };
                    mma_f16(acc[mt][nt], a[mt], bfr);
                }
        }
        __syncthreads();
    }

    // epilogue: store half
#pragma unroll
    for (int mt = 0; mt < 4; mt++) {
        int r0 = bm + wm + mt * 16 + (lane >> 2);
#pragma unroll
        for (int nt = 0; nt < 4; nt++) {
            int col = bn + wn + nt * 8 + (lane & 3) * 2;
            if (r0 < N_NODES)
                *(__half2*)(C + (size_t)r0 * HC + col) =
                    __floats2half2_rn(acc[mt][nt][0], acc[mt][nt][1]);
            if (r0 + 8 < N_NODES)
                *(__half2*)(C + (size_t)(r0 + 8) * HC + col) =
                    __floats2half2_rn(acc[mt][nt][2], acc[mt][nt][3]);
        }
    }
}

// ---------------- edge scores + segment max (warp/edge, half gathers) ------
__global__ void score_kernel(const int* __restrict__ ei,
                             const float* __restrict__ att) {
    int w = (blockIdx.x * blockDim.x + threadIdx.x) >> 5;
    int lane = threadIdx.x & 31;
    if (w >= E_TOT) return;
    int src, dst;
    if (w < N_EDGES) { src = ei[w]; dst = ei[N_EDGES + w]; }
    else             { src = dst = w - N_EDGES; }

    const uint4* __restrict__ xl = (const uint4*)(g_xl + (size_t)src * HC);
    const uint4* __restrict__ xr = (const uint4*)(g_xr + (size_t)dst * HC);
    const float4* __restrict__ at4 = (const float4*)att;

    float accs[4] = {0.f, 0.f, 0.f, 0.f};
#pragma unroll
    for (int it = 0; it < 8; it++) {
        int g = it * 32 + lane;             // uint4 group (8 halfs); head = it>>1
        uint4 a = xl[g];
        uint4 b = xr[g];
        float4 t0 = at4[2 * g], t1 = at4[2 * g + 1];
        const __half2* ha = (const __half2*)&a;
        const __half2* hb = (const __half2*)&b;
        float tt[8] = {t0.x, t0.y, t0.z, t0.w, t1.x, t1.y, t1.z, t1.w};
        float s = 0.f;
#pragma unroll
        for (int j = 0; j < 4; j++) {
            float2 fa = __half22float2(ha[j]);
            float2 fb = __half22float2(hb[j]);
            float u0 = fa.x + fb.x, u1 = fa.y + fb.y;
            u0 = u0 > 0.f ? u0 : NEG_SLOPE * u0;
            u1 = u1 > 0.f ? u1 : NEG_SLOPE * u1;
            s += u0 * tt[2 * j] + u1 * tt[2 * j + 1];
        }
        accs[it >> 1] += s;
    }
#pragma unroll
    for (int h = 0; h < 4; h++)
#pragma unroll
        for (int off = 16; off; off >>= 1)
            accs[h] += __shfl_xor_sync(0xFFFFFFFFu, accs[h], off);

    if (lane == 0) {
#pragma unroll
        for (int h = 0; h < 4; h++) {
            g_e[w * 4 + h] = accs[h];
            atomicMax(&g_mu[dst * 4 + h], fenc(accs[h]));
        }
    }
}

// ---------------- alpha = exp(e - m), denom = segment_sum ------------------
__global__ void alpha_kernel(const int* __restrict__ ei) {
    int t = blockIdx.x * blockDim.x + threadIdx.x;
    if (t >= E_TOT * HEADS) return;
    int k = t >> 2, h = t & 3;
    int dst = (k < N_EDGES) ? ei[N_EDGES + k] : (k - N_EDGES);
    float m = fdec(g_mu[dst * 4 + h]);
    float a = expf(g_e[t] - m);
    g_alpha[t] = a;
    atomicAdd(&g_denom[dst * 4 + h], a);
}

// ---------------- aggregation (warp/edge, half gathers, fp32 atomics) ------
__global__ void agg_kernel(const int* __restrict__ ei) {
    int w = (blockIdx.x * blockDim.x + threadIdx.x) >> 5;
    int lane = threadIdx.x & 31;
    if (w >= E_TOT) return;
    int src, dst;
    if (w < N_EDGES) { src = ei[w]; dst = ei[N_EDGES + w]; }
    else             { src = dst = w - N_EDGES; }

    float wt[4];
#pragma unroll
    for (int h = 0; h < 4; h++)
        wt[h] = 0.25f * g_alpha[w * 4 + h] / g_denom[dst * 4 + h];

    const uint2* __restrict__ row = (const uint2*)(g_xl + (size_t)src * HC);
    float* __restrict__ out = g_agg + (size_t)dst * FEAT;

#pragma unroll
    for (int it = 0; it < 4; it++) {
        int g = it * 32 + lane;             // 4-half group within head, < 128
        float rx = 0.f, ry = 0.f, rz = 0.f, rw = 0.f;
#pragma unroll
        for (int h = 0; h < 4; h++) {
            uint2 u = row[h * 128 + g];
            float2 f0 = __half22float2(*(const __half2*)&u.x);
            float2 f1 = __half22float2(*(const __half2*)&u.y);
            rx += wt[h] * f0.x; ry += wt[h] * f0.y;
            rz += wt[h] * f1.x; rw += wt[h] * f1.y;
        }
        int c = g * 4;
        atomicAdd(out + c + 0, rx);
        atomicAdd(out + c + 1, ry);
        atomicAdd(out + c + 2, rz);
        atomicAdd(out + c + 3, rw);
    }
}

// ---------------- head mean + bias + classifier (warp/node) ----------------
__global__ void head_kernel(const float* __restrict__ bias,
                            const float* __restrict__ Wc,
                            const float* __restrict__ bc,
                            float* __restrict__ out) {
    int n = (blockIdx.x * blockDim.x + threadIdx.x) >> 5;
    int lane = threadIdx.x & 31;
    if (n >= N_NODES) return;

    const float4* __restrict__ ag = (const float4*)(g_agg + (size_t)n * FEAT);
    const float4* __restrict__ bi = (const float4*)bias;

    float a0 = 0.f, a1 = 0.f;
#pragma unroll
    for (int it = 0; it < 4; it++) {
        int c4 = it * 32 + lane;
        float4 v = ag[c4];
        float4 b = bi[c4];
        float o0 = v.x + b.x, o1 = v.y + b.y, o2 = v.z + b.z, o3 = v.w + b.w;
        const float4* w4 = (const float4*)(Wc + (size_t)c4 * 8);
        float4 wA = w4[0];
        float4 wB = w4[1];
        a0 += o0 * wA.x + o1 * wA.z + o2 * wB.x + o3 * wB.z;
        a1 += o0 * wA.y + o1 * wA.w + o2 * wB.y + o3 * wB.w;
    }
#pragma unroll
    for (int off = 16; off; off >>= 1) {
        a0 += __shfl_xor_sync(0xFFFFFFFFu, a0, off);
        a1 += __shfl_xor_sync(0xFFFFFFFFu, a1, off);
    }
    if (lane == 0) {
        out[n * 2 + 0] = a0 + bc[0];
        out[n * 2 + 1] = a1 + bc[1];
    }
}

// ---------------- launch ---------------------------------------------------
extern "C" void kernel_launch(void* const* d_in, const int* in_sizes, int n_in,
                              void* d_out, int out_size) {
    const float* x    = (const float*)d_in[0];
    const int*   ei   = (const int*)  d_in[1];
    const float* Wl   = (const float*)d_in[2];
    const float* Wr   = (const float*)d_in[3];
    const float* att  = (const float*)d_in[4];
    const float* bias = (const float*)d_in[5];
    const float* Wc   = (const float*)d_in[6];
    const float* bc   = (const float*)d_in[7];
    float* out = (float*)d_out;

    init_kernel<<<2560, 256>>>();
    xcvt_kernel<<<(N_NODES * FEAT / 8 + 255) / 256, 256>>>(x);
    wtrans_kernel<<<dim3(HC / 32, FEAT / 32, 2), dim3(32, 8)>>>(Wl, Wr);

    dim3 ggrid(HC / 128, (N_NODES + 127) / 128, 2);   // (16, 157, 2)
    gemm_f16_kernel<<<ggrid, 256>>>();

    score_kernel<<<(E_TOT + 7) / 8, 256>>>(ei, att);
    alpha_kernel<<<(E_TOT * HEADS + 255) / 256, 256>>>(ei);
    agg_kernel<<<(E_TOT + 7) / 8, 256>>>(ei);
    head_kernel<<<(N_NODES + 7) / 8, 256>>>(bias, Wc, bc, out);
}